// round 1
// baseline (speedup 1.0000x reference)
#include <cuda_runtime.h>

#define N_USERS 100000
#define N_ITEMS 50000
#define N_NODES 150000  // N_USERS + N_ITEMS
#define EMBED   64
#define NNZ     4000000
#define BATCH   4096
// EMBED floats = 16 float4 per node row
#define ROW4    16
#define TOTAL4  (N_NODES * ROW4)

// Scratch (device globals: no runtime allocation, allowed by harness rules)
__device__ float g_E0[N_NODES * EMBED];
__device__ float g_E1[N_NODES * EMBED];
__device__ float g_acc[N_NODES * EMBED];

// ---------------------------------------------------------------------------
// init: E0 = concat(embed_user, embed_item); acc = E0; E1 = 0
// ---------------------------------------------------------------------------
__global__ void lgcn_init(const float4* __restrict__ eu,
                          const float4* __restrict__ ei) {
    float4* E0  = reinterpret_cast<float4*>(g_E0);
    float4* E1  = reinterpret_cast<float4*>(g_E1);
    float4* acc = reinterpret_cast<float4*>(g_acc);
    const int stride = gridDim.x * blockDim.x;
    const int user4 = N_USERS * ROW4;
    for (int i = blockIdx.x * blockDim.x + threadIdx.x; i < TOTAL4; i += stride) {
        float4 v = (i < user4) ? eu[i] : ei[i - user4];
        E0[i]  = v;
        acc[i] = v;
        E1[i]  = make_float4(0.f, 0.f, 0.f, 0.f);
    }
}

// ---------------------------------------------------------------------------
// SpMM scatter: dst[row[e]] += a[e] * src[col[e]]  (16 threads per edge)
// ---------------------------------------------------------------------------
__global__ void lgcn_spmm(const int*   __restrict__ row,
                          const int*   __restrict__ col,
                          const float* __restrict__ a,
                          const float4* __restrict__ src,
                          float4* __restrict__ dst) {
    const int gid     = blockIdx.x * blockDim.x + threadIdx.x;
    const int lane16  = gid & 15;
    const int group   = gid >> 4;
    const int ngroups = (gridDim.x * blockDim.x) >> 4;
    for (int e = group; e < NNZ; e += ngroups) {
        const int   r  = __ldg(row + e);
        const int   c  = __ldg(col + e);
        const float av = __ldg(a + e);
        float4 v = __ldg(src + (size_t)c * ROW4 + lane16);
        float4 m = make_float4(av * v.x, av * v.y, av * v.z, av * v.w);
        float4* p = dst + (size_t)r * ROW4 + lane16;
        asm volatile("red.global.add.v4.f32 [%0], {%1,%2,%3,%4};"
                     :: "l"(p), "f"(m.x), "f"(m.y), "f"(m.z), "f"(m.w)
                     : "memory");
    }
}

// ---------------------------------------------------------------------------
// accum: acc += newE ; zero the OTHER buffer (becomes next layer's dst)
// ---------------------------------------------------------------------------
__global__ void lgcn_accum_zero(const float4* __restrict__ newE,
                                float4* __restrict__ zeroBuf) {
    float4* acc = reinterpret_cast<float4*>(g_acc);
    const int stride = gridDim.x * blockDim.x;
    for (int i = blockIdx.x * blockDim.x + threadIdx.x; i < TOTAL4; i += stride) {
        float4 n = newE[i];
        float4 s = acc[i];
        acc[i] = make_float4(s.x + n.x, s.y + n.y, s.z + n.z, s.w + n.w);
        zeroBuf[i] = make_float4(0.f, 0.f, 0.f, 0.f);
    }
}

// acc += newE only (last layer: no zeroing needed)
__global__ void lgcn_accum(const float4* __restrict__ newE) {
    float4* acc = reinterpret_cast<float4*>(g_acc);
    const int stride = gridDim.x * blockDim.x;
    for (int i = blockIdx.x * blockDim.x + threadIdx.x; i < TOTAL4; i += stride) {
        float4 n = newE[i];
        float4 s = acc[i];
        acc[i] = make_float4(s.x + n.x, s.y + n.y, s.z + n.z, s.w + n.w);
    }
}

// ---------------------------------------------------------------------------
// gather: out = [acc[user]/4 ; acc[N_USERS+pos]/4 ; acc[N_USERS+neg]/4]
// 16 threads per output row
// ---------------------------------------------------------------------------
__global__ void lgcn_gather(const int* __restrict__ bu,
                            const int* __restrict__ bp,
                            const int* __restrict__ bn,
                            float4* __restrict__ out) {
    const float4* acc = reinterpret_cast<const float4*>(g_acc);
    const int tid  = blockIdx.x * blockDim.x + threadIdx.x;
    const int lane = tid & 15;
    const int r    = tid >> 4;
    if (r >= 3 * BATCH) return;
    const int which = r / BATCH;
    const int b     = r - which * BATCH;
    int node;
    if (which == 0)      node = __ldg(bu + b);
    else if (which == 1) node = N_USERS + __ldg(bp + b);
    else                 node = N_USERS + __ldg(bn + b);
    float4 v = acc[(size_t)node * ROW4 + lane];
    const float s = 0.25f;  // 1/(N_LAYERS+1)
    out[(size_t)r * ROW4 + lane] = make_float4(v.x * s, v.y * s, v.z * s, v.w * s);
}

// ---------------------------------------------------------------------------
// launch
// ---------------------------------------------------------------------------
extern "C" void kernel_launch(void* const* d_in, const int* in_sizes, int n_in,
                              void* d_out, int out_size) {
    const int*   batch_user = (const int*)  d_in[0];
    const int*   batch_pos  = (const int*)  d_in[1];
    const int*   batch_neg  = (const int*)  d_in[2];
    const float* embed_user = (const float*)d_in[3];
    const float* embed_item = (const float*)d_in[4];
    const int*   row_idx    = (const int*)  d_in[5];
    const int*   col_idx    = (const int*)  d_in[6];
    const float* a_vals     = (const float*)d_in[7];
    float* out = (float*)d_out;

    float4* E0  = nullptr;
    float4* E1  = nullptr;
    cudaGetSymbolAddress((void**)&E0, g_E0);
    cudaGetSymbolAddress((void**)&E1, g_E1);

    const int T = 256;
    const int initBlocks  = 2048;
    const int spmmBlocks  = 148 * 8;           // grid-stride, ~8 CTAs/SM
    const int gatherBlocks = (3 * BATCH * 16 + T - 1) / T;

    lgcn_init<<<initBlocks, T>>>((const float4*)embed_user,
                                 (const float4*)embed_item);

    // layer 1: E0 -> E1 ; acc += E1 ; zero E0
    lgcn_spmm<<<spmmBlocks, T>>>(row_idx, col_idx, a_vals, E0, E1);
    lgcn_accum_zero<<<initBlocks, T>>>(E1, E0);

    // layer 2: E1 -> E0 ; acc += E0 ; zero E1
    lgcn_spmm<<<spmmBlocks, T>>>(row_idx, col_idx, a_vals, E1, E0);
    lgcn_accum_zero<<<initBlocks, T>>>(E0, E1);

    // layer 3: E0 -> E1 ; acc += E1
    lgcn_spmm<<<spmmBlocks, T>>>(row_idx, col_idx, a_vals, E0, E1);
    lgcn_accum<<<initBlocks, T>>>(E1);

    lgcn_gather<<<gatherBlocks, T>>>(batch_user, batch_pos, batch_neg,
                                     (float4*)out);
}

// round 2
// speedup vs baseline: 2.3848x; 2.3848x over previous
#include <cuda_runtime.h>

#define N_USERS 100000
#define N_ITEMS 50000
#define N_NODES 150000  // N_USERS + N_ITEMS
#define EMBED   64
#define NNZ     4000000
#define BATCH   4096
#define ROW2    32            // EMBED floats = 32 float2
#define ROW4    16            // EMBED floats = 16 float4
#define TOTAL4  (N_NODES * ROW4)

// ---------------------------------------------------------------------------
// Device-global scratch (static allocation: allowed by harness rules)
// ---------------------------------------------------------------------------
__device__ float g_E0[N_NODES * EMBED];
__device__ float g_E1[N_NODES * EMBED];
__device__ float g_acc[N_NODES * EMBED];

__device__ int   g_cnt[N_NODES];    // degree histogram
__device__ int   g_off[N_NODES];    // exclusive offsets
__device__ int   g_cur[N_NODES];    // scatter cursors
__device__ int   g_bsum[256];       // block sums for scan (147 used)
__device__ int   g_col_s[NNZ];      // edge cols sorted by row
__device__ float g_a_s[NNZ];        // edge weights sorted by row

// ---------------------------------------------------------------------------
// init: E0 = concat(embed_user, embed_item); acc = E0
// ---------------------------------------------------------------------------
__global__ void lgcn_init(const float4* __restrict__ eu,
                          const float4* __restrict__ ei) {
    float4* E0  = reinterpret_cast<float4*>(g_E0);
    float4* acc = reinterpret_cast<float4*>(g_acc);
    const int stride = gridDim.x * blockDim.x;
    const int user4 = N_USERS * ROW4;
    for (int i = blockIdx.x * blockDim.x + threadIdx.x; i < TOTAL4; i += stride) {
        float4 v = (i < user4) ? eu[i] : ei[i - user4];
        E0[i]  = v;
        acc[i] = v;
    }
}

// ---------------------------------------------------------------------------
// CSR build: histogram -> 2-level exclusive scan -> scatter (counting sort)
// ---------------------------------------------------------------------------
__global__ void k_hist(const int* __restrict__ row) {
    const int stride = gridDim.x * blockDim.x;
    for (int e = blockIdx.x * blockDim.x + threadIdx.x; e < NNZ; e += stride)
        atomicAdd(&g_cnt[__ldg(row + e)], 1);   // no return -> RED
}

#define SCAN_B 1024
// per-block exclusive scan of g_cnt -> g_off, block totals -> g_bsum
__global__ void k_scan_local() {
    __shared__ int s[SCAN_B];
    const int tid = threadIdx.x;
    const int i = blockIdx.x * SCAN_B + tid;
    int v = (i < N_NODES) ? g_cnt[i] : 0;
    s[tid] = v;
    __syncthreads();
    #pragma unroll
    for (int d = 1; d < SCAN_B; d <<= 1) {
        int t = (tid >= d) ? s[tid - d] : 0;
        __syncthreads();
        s[tid] += t;
        __syncthreads();
    }
    if (i < N_NODES) g_off[i] = s[tid] - v;          // exclusive
    if (tid == SCAN_B - 1) g_bsum[blockIdx.x] = s[tid];
}

// single-block exclusive scan of the 147 block sums
__global__ void k_scan_bsum(int nblocks) {
    __shared__ int s[256];
    const int tid = threadIdx.x;
    int v = (tid < nblocks) ? g_bsum[tid] : 0;
    s[tid] = v;
    __syncthreads();
    #pragma unroll
    for (int d = 1; d < 256; d <<= 1) {
        int t = (tid >= d) ? s[tid - d] : 0;
        __syncthreads();
        s[tid] += t;
        __syncthreads();
    }
    if (tid < nblocks) g_bsum[tid] = s[tid] - v;     // exclusive
}

// add block offsets back; seed cursors
__global__ void k_scan_add() {
    const int i = blockIdx.x * blockDim.x + threadIdx.x;
    if (i >= N_NODES) return;
    int o = g_off[i] + g_bsum[i / SCAN_B];
    g_off[i] = o;
    g_cur[i] = o;
}

// scatter edges into row-sorted order
__global__ void k_scatter(const int* __restrict__ row,
                          const int* __restrict__ col,
                          const float* __restrict__ a) {
    const int stride = gridDim.x * blockDim.x;
    for (int e = blockIdx.x * blockDim.x + threadIdx.x; e < NNZ; e += stride) {
        const int r = __ldg(row + e);
        int p = atomicAdd(&g_cur[r], 1);
        g_col_s[p] = __ldg(col + e);
        g_a_s[p]   = __ldg(a + e);
    }
}

// ---------------------------------------------------------------------------
// CSR SpMM: one warp per node. Gather-only segment sum, fused acc update.
//   dst[n] = sum_j a_s[j] * src[col_s[j]];  acc[n] += dst[n]
// ---------------------------------------------------------------------------
template<bool WRITE_DST>
__global__ void lgcn_csr(const float2* __restrict__ src,
                         float2* __restrict__ dst) {
    const int warp = (blockIdx.x * blockDim.x + threadIdx.x) >> 5;
    const int lane = threadIdx.x & 31;
    if (warp >= N_NODES) return;
    const int s = g_off[warp];
    const int n = g_cnt[warp];

    float2 sum = make_float2(0.f, 0.f);
    #pragma unroll 4
    for (int j = 0; j < n; j++) {
        const int   c  = __ldg(g_col_s + s + j);
        const float av = __ldg(g_a_s + s + j);
        float2 v = __ldg(src + (size_t)c * ROW2 + lane);
        sum.x += av * v.x;
        sum.y += av * v.y;
    }
    const size_t o = (size_t)warp * ROW2 + lane;
    if (WRITE_DST) dst[o] = sum;
    float2* acc2 = reinterpret_cast<float2*>(g_acc);
    float2 a0 = acc2[o];
    acc2[o] = make_float2(a0.x + sum.x, a0.y + sum.y);
}

// ---------------------------------------------------------------------------
// gather: out = [acc[user] ; acc[N_USERS+pos] ; acc[N_USERS+neg]] * 0.25
// ---------------------------------------------------------------------------
__global__ void lgcn_gather(const int* __restrict__ bu,
                            const int* __restrict__ bp,
                            const int* __restrict__ bn,
                            float4* __restrict__ out) {
    const float4* acc = reinterpret_cast<const float4*>(g_acc);
    const int tid  = blockIdx.x * blockDim.x + threadIdx.x;
    const int lane = tid & 15;
    const int r    = tid >> 4;
    if (r >= 3 * BATCH) return;
    const int which = r / BATCH;
    const int b     = r - which * BATCH;
    int node;
    if (which == 0)      node = __ldg(bu + b);
    else if (which == 1) node = N_USERS + __ldg(bp + b);
    else                 node = N_USERS + __ldg(bn + b);
    float4 v = acc[(size_t)node * ROW4 + lane];
    const float sc = 0.25f;   // 1/(N_LAYERS+1)
    out[(size_t)r * ROW4 + lane] = make_float4(v.x * sc, v.y * sc, v.z * sc, v.w * sc);
}

// ---------------------------------------------------------------------------
// launch
// ---------------------------------------------------------------------------
extern "C" void kernel_launch(void* const* d_in, const int* in_sizes, int n_in,
                              void* d_out, int out_size) {
    const int*   batch_user = (const int*)  d_in[0];
    const int*   batch_pos  = (const int*)  d_in[1];
    const int*   batch_neg  = (const int*)  d_in[2];
    const float* embed_user = (const float*)d_in[3];
    const float* embed_item = (const float*)d_in[4];
    const int*   row_idx    = (const int*)  d_in[5];
    const int*   col_idx    = (const int*)  d_in[6];
    const float* a_vals     = (const float*)d_in[7];
    float* out = (float*)d_out;

    float2* E0 = nullptr;
    float2* E1 = nullptr;
    void*   cntp = nullptr;
    cudaGetSymbolAddress((void**)&E0, g_E0);
    cudaGetSymbolAddress((void**)&E1, g_E1);
    cudaGetSymbolAddress(&cntp, g_cnt);

    const int T = 256;
    const int initBlocks   = 2048;
    const int edgeBlocks   = 148 * 8;
    const int scanBlocks   = (N_NODES + SCAN_B - 1) / SCAN_B;     // 147
    const int addBlocks    = (N_NODES + T - 1) / T;
    const int csrBlocks    = (N_NODES * 32 + T - 1) / T;          // warp/node
    const int gatherBlocks = (3 * BATCH * 16 + T - 1) / T;

    // init embeddings + zero histogram (parallel-safe: same stream, ordered)
    cudaMemsetAsync(cntp, 0, N_NODES * sizeof(int));
    lgcn_init<<<initBlocks, T>>>((const float4*)embed_user,
                                 (const float4*)embed_item);

    // build CSR (counting sort by row)
    k_hist<<<edgeBlocks, T>>>(row_idx);
    k_scan_local<<<scanBlocks, SCAN_B>>>();
    k_scan_bsum<<<1, 256>>>(scanBlocks);
    k_scan_add<<<addBlocks, T>>>();
    k_scatter<<<edgeBlocks, T>>>(row_idx, col_idx, a_vals);

    // 3 propagation layers, acc fused
    lgcn_csr<true ><<<csrBlocks, T>>>(E0, E1);   // layer 1: E0 -> E1
    lgcn_csr<true ><<<csrBlocks, T>>>(E1, E0);   // layer 2: E1 -> E0
    lgcn_csr<false><<<csrBlocks, T>>>(E0, E1);   // layer 3: acc only

    lgcn_gather<<<gatherBlocks, T>>>(batch_user, batch_pos, batch_neg,
                                     (float4*)out);
}